// round 1
// baseline (speedup 1.0000x reference)
#include <cuda_runtime.h>
#include <math.h>

// Problem constants
#define Bb 16
#define Dd 384
#define Nn_ 8192
#define HEADS 8
#define DIMH 64
#define Hh 512          // HEADS*DIMH
#define SCALE 0.125f    // 64^-0.5
#define EPSLN 1e-5f
#define NSPLIT 8

// ---------------- static scratch (no allocations allowed) ----------------
__device__ float g_mean[(long)Bb * Nn_];
__device__ float g_rstd[(long)Bb * Nn_];
__device__ float g_kv[(long)Bb * 1024 * Nn_];          // rows 0..511 = k(h,d), 512..1023 = v(h,e)
__device__ float g_rowmax[Bb * 512];
__device__ float g_rowinv[Bb * 512];
__device__ float g_ctxpart[(long)NSPLIT * 128 * 64 * 64];
__device__ float g_T[(long)Bb * 384 * 512];
__device__ float g_wfinal[(long)Bb * 384 * 384];

// ---------------- LayerNorm stats: mean / rstd per (b,n) ----------------
__global__ void ln_stats_kernel(const float* __restrict__ x,
                                float* __restrict__ meanp,
                                float* __restrict__ rstdp) {
    long g = (long)blockIdx.x * blockDim.x + threadIdx.x;   // 0..B*N-1
    long b = g / Nn_;
    long n = g - b * Nn_;
    const float* p = x + b * (long)Dd * Nn_ + n;
    float s = 0.f, sq = 0.f;
    #pragma unroll 4
    for (int d = 0; d < Dd; d++) {
        float v = p[(long)d * Nn_];
        s += v; sq += v * v;
    }
    float mean = s * (1.0f / Dd);
    float var = sq * (1.0f / Dd) - mean * mean;
    meanp[g] = mean;
    rstdp[g] = rsqrtf(var + EPSLN);
}

// ---------------- tiled SGEMM, 128x128x8, 256 thr, 8x8 per thread --------
// C[bz] = A[bz] (MxK, lda=K) * B[bz] (KxN, ldb=N), optional LN on B-load,
// optional epilogue (bias+residual) or scale.
template<bool LN_B, bool EPI_FINAL, bool EPI_SCALE>
__global__ __launch_bounds__(256)
void sgemm_k(const float* __restrict__ A, const float* __restrict__ Bsrc,
             float* __restrict__ C,
             int M, int K, int Nc,
             long sA, long sB, long sC,
             const float* __restrict__ meanp, const float* __restrict__ rstdp,
             long sStat,
             const float* __restrict__ gamma, const float* __restrict__ beta,
             const float* __restrict__ bias, const float* __restrict__ resid,
             long sRes, float scaleC) {
    const int BM = 128, BN = 128, BK = 8;
    __shared__ float As[BK][BM];
    __shared__ float Bs[BK][BN];
    __shared__ float meanS[BN];
    __shared__ float rstdS[BN];

    int tid = threadIdx.x;
    int bz = blockIdx.z;
    A    += (long)bz * sA;
    Bsrc += (long)bz * sB;
    C    += (long)bz * sC;
    const float* residp = nullptr;
    if (EPI_FINAL) residp = resid + (long)bz * sRes;

    int bn0 = blockIdx.x * BN;
    int bm0 = blockIdx.y * BM;

    if (LN_B) {
        if (tid < BN) {
            long so = (long)bz * sStat + bn0 + tid;
            meanS[tid] = meanp[so];
            rstdS[tid] = rstdp[so];
        }
    }
    __syncthreads();

    int ar = tid >> 1, ac = (tid & 1) * 4;     // A tile loader: 128 rows x 8 k
    int br = tid >> 5, bc = (tid & 31) * 4;    // B tile loader: 8 k x 128 n
    int tx = tid & 15, ty = tid >> 4;

    float acc[8][8];
    #pragma unroll
    for (int i = 0; i < 8; i++)
        #pragma unroll
        for (int j = 0; j < 8; j++) acc[i][j] = 0.f;

    const float* Aptr = A + (long)(bm0 + ar) * K + ac;
    const float* Bptr = Bsrc + (long)br * Nc + bn0 + bc;

    for (int k0 = 0; k0 < K; k0 += BK) {
        float4 av = *(const float4*)(Aptr + k0);
        float4 bv = *(const float4*)(Bptr + (long)k0 * Nc);
        if (LN_B) {
            float gg = gamma[k0 + br];
            float bb = beta[k0 + br];
            bv.x = (bv.x - meanS[bc + 0]) * rstdS[bc + 0] * gg + bb;
            bv.y = (bv.y - meanS[bc + 1]) * rstdS[bc + 1] * gg + bb;
            bv.z = (bv.z - meanS[bc + 2]) * rstdS[bc + 2] * gg + bb;
            bv.w = (bv.w - meanS[bc + 3]) * rstdS[bc + 3] * gg + bb;
        }
        As[ac + 0][ar] = av.x;
        As[ac + 1][ar] = av.y;
        As[ac + 2][ar] = av.z;
        As[ac + 3][ar] = av.w;
        *(float4*)&Bs[br][bc] = bv;
        __syncthreads();

        #pragma unroll
        for (int kk = 0; kk < BK; kk++) {
            float a[8], b2[8];
            *(float4*)&a[0]  = *(const float4*)&As[kk][ty * 8];
            *(float4*)&a[4]  = *(const float4*)&As[kk][ty * 8 + 4];
            *(float4*)&b2[0] = *(const float4*)&Bs[kk][tx * 8];
            *(float4*)&b2[4] = *(const float4*)&Bs[kk][tx * 8 + 4];
            #pragma unroll
            for (int i = 0; i < 8; i++)
                #pragma unroll
                for (int j = 0; j < 8; j++)
                    acc[i][j] += a[i] * b2[j];
        }
        __syncthreads();
    }

    #pragma unroll
    for (int i = 0; i < 8; i++) {
        int row = bm0 + ty * 8 + i;
        long base = (long)row * Nc + bn0 + tx * 8;
        float rb = 0.f;
        if (EPI_FINAL) rb = bias[row];
        #pragma unroll
        for (int j = 0; j < 8; j += 4) {
            float4 v;
            v.x = acc[i][j + 0];
            v.y = acc[i][j + 1];
            v.z = acc[i][j + 2];
            v.w = acc[i][j + 3];
            if (EPI_SCALE) {
                v.x *= scaleC; v.y *= scaleC; v.z *= scaleC; v.w *= scaleC;
            }
            if (EPI_FINAL) {
                float4 r = *(const float4*)&residp[base + j];
                v.x += rb + r.x; v.y += rb + r.y; v.z += rb + r.z; v.w += rb + r.w;
            }
            *(float4*)&C[base + j] = v;
        }
    }
}

// ---------------- softmax row stats over N for k rows --------------------
__global__ void softmax_stats_kernel(const float* __restrict__ kv,
                                     float* __restrict__ rowmax,
                                     float* __restrict__ rowinv) {
    int r = blockIdx.x;          // b*512 + (h*64+d)
    int b = r >> 9;
    int m = r & 511;
    const float* p = kv + ((long)b * 1024 + m) * Nn_;
    int tid = threadIdx.x;

    float vals[32];
    float mx = -1e30f;
    #pragma unroll
    for (int i = 0; i < 32; i++) {
        vals[i] = p[tid + i * 256];
        mx = fmaxf(mx, vals[i]);
    }
    __shared__ float red[256];
    red[tid] = mx;
    __syncthreads();
    for (int s = 128; s > 0; s >>= 1) {
        if (tid < s) red[tid] = fmaxf(red[tid], red[tid + s]);
        __syncthreads();
    }
    mx = red[0];
    __syncthreads();

    float sm = 0.f;
    #pragma unroll
    for (int i = 0; i < 32; i++) sm += __expf(vals[i] - mx);
    red[tid] = sm;
    __syncthreads();
    for (int s = 128; s > 0; s >>= 1) {
        if (tid < s) red[tid] += red[tid + s];
        __syncthreads();
    }
    if (tid == 0) {
        rowmax[r] = mx;
        rowinv[r] = 1.0f / red[0];
    }
}

// ---------------- partial context: ctx_part[sp][bh][d][e] ----------------
__global__ void context_part_kernel(const float* __restrict__ kv,
                                    const float* __restrict__ rowmax,
                                    float* __restrict__ ctx_part) {
    int bid = blockIdx.x;               // bh*NSPLIT + sp
    int bh = bid / NSPLIT, sp = bid % NSPLIT;
    int b = bh >> 3, h = bh & 7;
    const float* kbase = kv + ((long)b * 1024 + h * 64) * Nn_;
    const float* vbase = kv + ((long)b * 1024 + 512 + h * 64) * Nn_;
    const float* rmax = rowmax + b * 512 + h * 64;

    __shared__ float Ks[64][65];
    __shared__ float Vs[64][65];
    __shared__ float rmaxS[64];
    int tid = threadIdx.x;
    if (tid < 64) rmaxS[tid] = rmax[tid];
    __syncthreads();

    float acc[4][4];
    #pragma unroll
    for (int i = 0; i < 4; i++)
        #pragma unroll
        for (int j = 0; j < 4; j++) acc[i][j] = 0.f;

    int tx = tid & 15, ty = tid >> 4;
    int n0sp = sp * (Nn_ / NSPLIT);
    int n1sp = n0sp + (Nn_ / NSPLIT);

    for (int n0 = n0sp; n0 < n1sp; n0 += 64) {
        #pragma unroll
        for (int i = 0; i < 16; i++) {
            int idx = tid + i * 256;
            int d = idx >> 6, nn = idx & 63;
            Ks[d][nn] = __expf(kbase[(long)d * Nn_ + n0 + nn] - rmaxS[d]);
            Vs[d][nn] = vbase[(long)d * Nn_ + n0 + nn];
        }
        __syncthreads();
        #pragma unroll 4
        for (int nn = 0; nn < 64; nn++) {
            float kr[4], vr[4];
            #pragma unroll
            for (int i = 0; i < 4; i++) kr[i] = Ks[ty * 4 + i][nn];
            #pragma unroll
            for (int j = 0; j < 4; j++) vr[j] = Vs[tx * 4 + j][nn];
            #pragma unroll
            for (int i = 0; i < 4; i++)
                #pragma unroll
                for (int j = 0; j < 4; j++)
                    acc[i][j] += kr[i] * vr[j];
        }
        __syncthreads();
    }

    float* cp = ctx_part + ((long)sp * 128 + bh) * 4096;
    #pragma unroll
    for (int i = 0; i < 4; i++)
        #pragma unroll
        for (int j = 0; j < 4; j++)
            cp[(ty * 4 + i) * 64 + tx * 4 + j] = acc[i][j];
}

// ------------- T[b][d][(h,dd)] = sum_e w_out[d,(h,e)] * ctx[b,h,dd,e] ----
__global__ void build_T_kernel(const float* __restrict__ ctx_part,
                               const float* __restrict__ rowinv,
                               const float* __restrict__ wout,
                               float* __restrict__ T) {
    int bh = blockIdx.x;
    int b = bh >> 3, h = bh & 7;
    __shared__ float ctxS[64][65];
    __shared__ float wS[64][65];
    int tid = threadIdx.x;

    // reduce partials, apply 1/rowsum (per k-row d)
    #pragma unroll
    for (int i = 0; i < 16; i++) {
        int idx = tid + i * 256;
        int d = idx >> 6, e = idx & 63;
        float s = 0.f;
        #pragma unroll
        for (int sp = 0; sp < NSPLIT; sp++)
            s += ctx_part[((long)sp * 128 + bh) * 4096 + idx];
        ctxS[d][e] = s * rowinv[b * 512 + h * 64 + d];
    }
    __syncthreads();

    float* Tb = T + (long)b * 384 * 512;
    for (int c = 0; c < 6; c++) {                 // 6 chunks of 64 output rows d
        #pragma unroll
        for (int i = 0; i < 16; i++) {
            int idx = tid + i * 256;
            int dr = idx >> 6, e = idx & 63;
            wS[dr][e] = wout[(long)(c * 64 + dr) * Hh + h * 64 + e];
        }
        __syncthreads();
        #pragma unroll
        for (int i = 0; i < 16; i++) {
            int idx = tid + i * 256;
            int dl = idx >> 6, dd = idx & 63;
            float s = 0.f;
            #pragma unroll
            for (int e = 0; e < 64; e++)
                s += wS[dl][e] * ctxS[dd][e];
            Tb[(long)(c * 64 + dl) * 512 + h * 64 + dd] = s;
        }
        __syncthreads();
    }
}

// -------------------------------------------------------------------------
extern "C" void kernel_launch(void* const* d_in, const int* in_sizes, int n_in,
                              void* d_out, int out_size) {
    (void)in_sizes; (void)n_in; (void)out_size;
    const float* x     = (const float*)d_in[0];
    const float* gam   = (const float*)d_in[1];
    const float* bet   = (const float*)d_in[2];
    const float* w_qkv = (const float*)d_in[3];
    const float* w_out = (const float*)d_in[4];
    const float* b_out = (const float*)d_in[5];
    float* out = (float*)d_out;

    float *p_mean, *p_rstd, *p_kv, *p_rowmax, *p_rowinv, *p_ctxp, *p_T, *p_wf;
    cudaGetSymbolAddress((void**)&p_mean,   g_mean);
    cudaGetSymbolAddress((void**)&p_rstd,   g_rstd);
    cudaGetSymbolAddress((void**)&p_kv,     g_kv);
    cudaGetSymbolAddress((void**)&p_rowmax, g_rowmax);
    cudaGetSymbolAddress((void**)&p_rowinv, g_rowinv);
    cudaGetSymbolAddress((void**)&p_ctxp,   g_ctxpart);
    cudaGetSymbolAddress((void**)&p_T,      g_T);
    cudaGetSymbolAddress((void**)&p_wf,     g_wfinal);

    // 1. LN stats
    ln_stats_kernel<<<(Bb * Nn_) / 256, 256>>>(x, p_mean, p_rstd);

    // 2. k,v = W_kv @ LN(x)   (M=1024, K=384, N=8192, batched over B)
    sgemm_k<true, false, false><<<dim3(Nn_ / 128, 1024 / 128, Bb), 256>>>(
        w_qkv + (long)512 * Dd, x, p_kv,
        1024, Dd, Nn_,
        0L, (long)Dd * Nn_, (long)1024 * Nn_,
        p_mean, p_rstd, (long)Nn_,
        gam, bet, nullptr, nullptr, 0L, 1.0f);

    // 3. softmax stats per k row
    softmax_stats_kernel<<<Bb * 512, 256>>>(p_kv, p_rowmax, p_rowinv);

    // 4. partial contexts
    context_part_kernel<<<128 * NSPLIT, 256>>>(p_kv, p_rowmax, p_ctxp);

    // 5. T = w_out(head) contracted with ctx
    build_T_kernel<<<128, 256>>>(p_ctxp, p_rowinv, w_out, p_T);

    // 6. W_final[b] = SCALE * T[b] @ W_q   (M=384, K=512, N=384)
    sgemm_k<false, false, true><<<dim3(384 / 128, 384 / 128, Bb), 256>>>(
        p_T, w_qkv, p_wf,
        384, 512, 384,
        (long)384 * 512, 0L, (long)384 * 384,
        nullptr, nullptr, 0L,
        nullptr, nullptr, nullptr, nullptr, 0L, SCALE);

    // 7. out = W_final[b] @ LN(x) + b_out + x   (M=384, K=384, N=8192)
    sgemm_k<true, true, false><<<dim3(Nn_ / 128, 384 / 128, Bb), 256>>>(
        p_wf, x, out,
        384, Dd, Nn_,
        (long)384 * 384, (long)Dd * Nn_, (long)Dd * Nn_,
        p_mean, p_rstd, (long)Nn_,
        gam, bet, b_out, x, (long)Dd * Nn_, 1.0f);
}

// round 2
// speedup vs baseline: 5.9417x; 5.9417x over previous
#include <cuda_runtime.h>
#include <cuda_bf16.h>
#include <math.h>

#define Bb 16
#define Dd 384
#define Nn_ 8192
#define Hh 512
#define SCALE 0.125f
#define EPSLN 1e-5f
#define NSPLIT 16

// ---------------- static scratch ----------------
__device__ __nv_bfloat16 g_xn[(long)Bb * Dd * Nn_];        // LN(x), bf16, [b][d][n]
__device__ __nv_bfloat16 g_kv[(long)Bb * 1024 * Nn_];      // k rows 0..511, v rows 512..1023
__device__ float         g_ctxpart[(long)NSPLIT * 128 * 4096];
__device__ float         g_rowsum[Bb * 512];
__device__ __nv_bfloat16 g_T[(long)Bb * 384 * 512];
__device__ __nv_bfloat16 g_wf[(long)Bb * 384 * 384];
__device__ __nv_bfloat16 g_wqkv_bf[1536 * 384];

// ---------------- helpers ----------------
__device__ __forceinline__ void ldsm_x4(unsigned addr, unsigned &r0, unsigned &r1,
                                        unsigned &r2, unsigned &r3) {
    asm volatile("ldmatrix.sync.aligned.m8n8.x4.shared.b16 {%0,%1,%2,%3}, [%4];\n"
                 : "=r"(r0), "=r"(r1), "=r"(r2), "=r"(r3) : "r"(addr));
}
__device__ __forceinline__ void ldsm_x4_t(unsigned addr, unsigned &r0, unsigned &r1,
                                          unsigned &r2, unsigned &r3) {
    asm volatile("ldmatrix.sync.aligned.m8n8.x4.trans.shared.b16 {%0,%1,%2,%3}, [%4];\n"
                 : "=r"(r0), "=r"(r1), "=r"(r2), "=r"(r3) : "r"(addr));
}
__device__ __forceinline__ void mma16816(float *c, const unsigned *a, unsigned b0, unsigned b1) {
    asm volatile("mma.sync.aligned.m16n8k16.row.col.f32.bf16.bf16.f32 "
                 "{%0,%1,%2,%3}, {%4,%5,%6,%7}, {%8,%9}, {%0,%1,%2,%3};\n"
                 : "+f"(c[0]), "+f"(c[1]), "+f"(c[2]), "+f"(c[3])
                 : "r"(a[0]), "r"(a[1]), "r"(a[2]), "r"(a[3]), "r"(b0), "r"(b1));
}

// ---------------- fp32 -> bf16 weight convert ----------------
__global__ void cvt_kernel(const float* __restrict__ src, __nv_bfloat16* __restrict__ dst, int n) {
    int i = blockIdx.x * blockDim.x + threadIdx.x;
    if (i < n) dst[i] = __float2bfloat16(src[i]);
}

// ---------------- LayerNorm -> bf16 x_norm (one x read) ----------------
__global__ __launch_bounds__(256) void ln_norm_kernel(const float* __restrict__ x,
                                                      const float* __restrict__ gamma,
                                                      const float* __restrict__ beta,
                                                      __nv_bfloat16* __restrict__ xn) {
    __shared__ float gS[384], bS[384];
    __shared__ float red_s[8][33], red_q[8][33];
    __shared__ float mS[32], rS[32];
    int tid = threadIdx.x;
    int dg = tid >> 5, tn = tid & 31;
    int b = blockIdx.y;
    int n = blockIdx.x * 32 + tn;
    for (int i = tid; i < 384; i += 256) { gS[i] = gamma[i]; bS[i] = beta[i]; }
    const float* xp = x + (long)b * Dd * Nn_ + n;
    float v[48];
    float s = 0.f, q = 0.f;
    #pragma unroll
    for (int i = 0; i < 48; i++) {
        int d = dg + i * 8;
        v[i] = xp[(long)d * Nn_];
        s += v[i]; q += v[i] * v[i];
    }
    red_s[dg][tn] = s; red_q[dg][tn] = q;
    __syncthreads();
    if (dg == 0) {
        float ts = 0.f, tq = 0.f;
        #pragma unroll
        for (int j = 0; j < 8; j++) { ts += red_s[j][tn]; tq += red_q[j][tn]; }
        float mean = ts * (1.0f / Dd);
        float var = tq * (1.0f / Dd) - mean * mean;
        mS[tn] = mean; rS[tn] = rsqrtf(var + EPSLN);
    }
    __syncthreads();
    float mean = mS[tn], rstd = rS[tn];
    __nv_bfloat16* xo = xn + (long)b * Dd * Nn_ + n;
    #pragma unroll
    for (int i = 0; i < 48; i++) {
        int d = dg + i * 8;
        xo[(long)d * Nn_] = __float2bfloat16((v[i] - mean) * rstd * gS[d] + bS[d]);
    }
}

// ---------------- bf16 tensor-core GEMM ----------------
// C[bz] = A[bz](MxK bf16) @ B[bz](KxN bf16).  EPI: 0 bf16 out, 1 bf16 out*scale,
// 2 fp32 out + bias[row] + resid.
template<int EPI>
__global__ __launch_bounds__(256)
void gemm_bf16_k(const __nv_bfloat16* __restrict__ A, const __nv_bfloat16* __restrict__ B,
                 void* __restrict__ Cv, int M, int K, int N,
                 long sA, long sB, long sC,
                 const float* __restrict__ bias,
                 const float* __restrict__ resid, long sRes, float scale) {
    __shared__ __align__(16) __nv_bfloat16 As[2][128 * 40];
    __shared__ __align__(16) __nv_bfloat16 Bs[2][32 * 136];
    int tid = threadIdx.x, lane = tid & 31, wid = tid >> 5;
    int bz = blockIdx.z;
    A += (long)bz * sA; B += (long)bz * sB;
    int bm0 = blockIdx.x * 128, bn0 = blockIdx.y * 128;

    // global loader addresses
    const __nv_bfloat16* Ag0 = A + (long)(bm0 + (tid >> 2)) * K + (tid & 3) * 8;
    const __nv_bfloat16* Ag1 = Ag0 + (long)64 * K;
    const __nv_bfloat16* Bg0 = B + (long)(tid >> 4) * N + bn0 + (tid & 15) * 8;
    const __nv_bfloat16* Bg1 = Bg0 + (long)16 * N;
    int ao = (tid >> 2) * 40 + (tid & 3) * 8;
    int bo = (tid >> 4) * 136 + (tid & 15) * 8;

    int gid = lane >> 2, tid4 = lane & 3;
    int rsel = lane & 15, csel = (lane >> 4) * 8;
    int wm = (wid & 1) * 64, wn = (wid >> 1) * 32;

    float acc[4][4][4];
    #pragma unroll
    for (int i = 0; i < 4; i++)
        #pragma unroll
        for (int j = 0; j < 4; j++)
            #pragma unroll
            for (int k = 0; k < 4; k++) acc[i][j][k] = 0.f;

    uint4 pa0, pa1, pb0, pb1;
    int nch = K / 32;

    // preload chunk 0
    pa0 = *(const uint4*)(Ag0); pa1 = *(const uint4*)(Ag1);
    pb0 = *(const uint4*)(Bg0); pb1 = *(const uint4*)(Bg1);
    *(uint4*)&As[0][ao] = pa0; *(uint4*)&As[0][ao + 64 * 40] = pa1;
    *(uint4*)&Bs[0][bo] = pb0; *(uint4*)&Bs[0][bo + 16 * 136] = pb1;
    __syncthreads();

    for (int c = 0; c < nch; c++) {
        int buf = c & 1;
        if (c + 1 < nch) {
            int k0 = (c + 1) * 32;
            pa0 = *(const uint4*)(Ag0 + k0);
            pa1 = *(const uint4*)(Ag1 + k0);
            pb0 = *(const uint4*)(Bg0 + (long)k0 * N);
            pb1 = *(const uint4*)(Bg1 + (long)k0 * N);
        }
        #pragma unroll
        for (int ks = 0; ks < 32; ks += 16) {
            unsigned a[4][4], bf[2][4];
            #pragma unroll
            for (int mt = 0; mt < 4; mt++) {
                unsigned addr = (unsigned)__cvta_generic_to_shared(
                    &As[buf][(wm + mt * 16 + rsel) * 40 + ks + csel]);
                ldsm_x4(addr, a[mt][0], a[mt][1], a[mt][2], a[mt][3]);
            }
            #pragma unroll
            for (int nt2 = 0; nt2 < 2; nt2++) {
                unsigned addr = (unsigned)__cvta_generic_to_shared(
                    &Bs[buf][(ks + rsel) * 136 + wn + nt2 * 16 + csel]);
                ldsm_x4_t(addr, bf[nt2][0], bf[nt2][1], bf[nt2][2], bf[nt2][3]);
            }
            #pragma unroll
            for (int mt = 0; mt < 4; mt++)
                #pragma unroll
                for (int nt = 0; nt < 4; nt++)
                    mma16816(acc[mt][nt], a[mt], bf[nt >> 1][(nt & 1) * 2],
                             bf[nt >> 1][(nt & 1) * 2 + 1]);
        }
        if (c + 1 < nch) {
            int nb = (c + 1) & 1;
            *(uint4*)&As[nb][ao] = pa0; *(uint4*)&As[nb][ao + 64 * 40] = pa1;
            *(uint4*)&Bs[nb][bo] = pb0; *(uint4*)&Bs[nb][bo + 16 * 136] = pb1;
        }
        __syncthreads();
    }

    // epilogue
    #pragma unroll
    for (int mt = 0; mt < 4; mt++) {
        int row = bm0 + wm + mt * 16 + gid;
        #pragma unroll
        for (int nt = 0; nt < 4; nt++) {
            int col = bn0 + wn + nt * 8 + 2 * tid4;
            float c0 = acc[mt][nt][0], c1 = acc[mt][nt][1];
            float c2 = acc[mt][nt][2], c3 = acc[mt][nt][3];
            if (EPI == 0 || EPI == 1) {
                if (EPI == 1) { c0 *= scale; c1 *= scale; c2 *= scale; c3 *= scale; }
                __nv_bfloat16* Cb = (__nv_bfloat16*)Cv + (long)bz * sC;
                *(__nv_bfloat162*)&Cb[(long)row * N + col] = __floats2bfloat162_rn(c0, c1);
                *(__nv_bfloat162*)&Cb[(long)(row + 8) * N + col] = __floats2bfloat162_rn(c2, c3);
            } else {
                float* Cf = (float*)Cv + (long)bz * sC;
                const float* rp = resid + (long)bz * sRes;
                float bz1 = bias[row], bz2 = bias[row + 8];
                float2 r1 = *(const float2*)&rp[(long)row * N + col];
                float2 r2 = *(const float2*)&rp[(long)(row + 8) * N + col];
                float2 o1 = make_float2(c0 + bz1 + r1.x, c1 + bz1 + r1.y);
                float2 o2 = make_float2(c2 + bz2 + r2.x, c3 + bz2 + r2.y);
                *(float2*)&Cf[(long)row * N + col] = o1;
                *(float2*)&Cf[(long)(row + 8) * N + col] = o2;
            }
        }
    }
}

// ---------------- row sums of exp(k) ----------------
__global__ __launch_bounds__(256) void rowsum_kernel(const __nv_bfloat16* __restrict__ kv,
                                                     float* __restrict__ rowsum) {
    int r = blockIdx.x;            // b*512 + m
    int b = r >> 9, m = r & 511;
    const uint4* p = (const uint4*)(kv + ((long)b * 1024 + m) * Nn_);
    int tid = threadIdx.x;
    float s = 0.f;
    for (int u = tid; u < Nn_ / 8; u += 256) {
        uint4 w = p[u];
        __nv_bfloat162* h = (__nv_bfloat162*)&w;
        #pragma unroll
        for (int i = 0; i < 4; i++) {
            float2 f = __bfloat1622float2(h[i]);
            s += __expf(f.x) + __expf(f.y);
        }
    }
    __shared__ float red[256];
    red[tid] = s;
    __syncthreads();
    for (int st = 128; st > 0; st >>= 1) {
        if (tid < st) red[tid] += red[tid + st];
        __syncthreads();
    }
    if (tid == 0) rowsum[r] = red[0];
}

// ---------------- context via mma: ctx_part[sp][bh][d][e] ----------------
__device__ __forceinline__ uint4 exp8(uint4 w) {
    __nv_bfloat162* h = (__nv_bfloat162*)&w;
    #pragma unroll
    for (int i = 0; i < 4; i++) {
        float2 f = __bfloat1622float2(h[i]);
        h[i] = __floats2bfloat162_rn(__expf(f.x), __expf(f.y));
    }
    return w;
}

__global__ __launch_bounds__(256) void context_mma_kernel(const __nv_bfloat16* __restrict__ kv,
                                                          float* __restrict__ ctx_part) {
    __shared__ __align__(16) __nv_bfloat16 Ks[2][64 * 72];
    __shared__ __align__(16) __nv_bfloat16 Vs[2][64 * 72];
    const int LEN = Nn_ / NSPLIT;          // 512
    int sp = blockIdx.x, bh = blockIdx.y;
    int b = bh >> 3, h = bh & 7;
    const __nv_bfloat16* kb = kv + ((long)b * 1024 + h * 64) * Nn_;
    const __nv_bfloat16* vb = kv + ((long)b * 1024 + 512 + h * 64) * Nn_;
    int tid = threadIdx.x, lane = tid & 31, wid = tid >> 5;
    int lr = tid >> 3, lc = (tid & 7) * 8;
    int n0 = sp * LEN;
    int gid = lane >> 2, tid4 = lane & 3;
    int rsel = lane & 15, csel = (lane >> 4) * 8;
    int wm = (wid & 1) * 32, wn = (wid >> 1) * 16;

    float acc[2][2][4];
    #pragma unroll
    for (int i = 0; i < 2; i++)
        #pragma unroll
        for (int j = 0; j < 2; j++)
            #pragma unroll
            for (int k = 0; k < 4; k++) acc[i][j][k] = 0.f;

    uint4 k0v, k1v, v0v, v1v;
    const int NCH = LEN / 64;              // 8
    int so = lr * 72 + lc;

    // preload
    k0v = exp8(*(const uint4*)(kb + (long)lr * Nn_ + n0 + lc));
    k1v = exp8(*(const uint4*)(kb + (long)(lr + 32) * Nn_ + n0 + lc));
    v0v = *(const uint4*)(vb + (long)lr * Nn_ + n0 + lc);
    v1v = *(const uint4*)(vb + (long)(lr + 32) * Nn_ + n0 + lc);
    *(uint4*)&Ks[0][so] = k0v; *(uint4*)&Ks[0][so + 32 * 72] = k1v;
    *(uint4*)&Vs[0][so] = v0v; *(uint4*)&Vs[0][so + 32 * 72] = v1v;
    __syncthreads();

    for (int c = 0; c < NCH; c++) {
        int buf = c & 1;
        if (c + 1 < NCH) {
            int off = n0 + (c + 1) * 64 + lc;
            k0v = exp8(*(const uint4*)(kb + (long)lr * Nn_ + off));
            k1v = exp8(*(const uint4*)(kb + (long)(lr + 32) * Nn_ + off));
            v0v = *(const uint4*)(vb + (long)lr * Nn_ + off);
            v1v = *(const uint4*)(vb + (long)(lr + 32) * Nn_ + off);
        }
        #pragma unroll
        for (int ks = 0; ks < 64; ks += 16) {
            unsigned a[2][4], bf[4];
            #pragma unroll
            for (int mt = 0; mt < 2; mt++) {
                unsigned addr = (unsigned)__cvta_generic_to_shared(
                    &Ks[buf][(wm + mt * 16 + rsel) * 72 + ks + csel]);
                ldsm_x4(addr, a[mt][0], a[mt][1], a[mt][2], a[mt][3]);
            }
            {
                unsigned addr = (unsigned)__cvta_generic_to_shared(
                    &Vs[buf][(wn + rsel) * 72 + ks + csel]);
                ldsm_x4(addr, bf[0], bf[1], bf[2], bf[3]);
            }
            #pragma unroll
            for (int mt = 0; mt < 2; mt++)
                #pragma unroll
                for (int nt = 0; nt < 2; nt++)
                    mma16816(acc[mt][nt], a[mt], bf[nt], bf[nt + 2]);
        }
        if (c + 1 < NCH) {
            int nb = (c + 1) & 1;
            *(uint4*)&Ks[nb][so] = k0v; *(uint4*)&Ks[nb][so + 32 * 72] = k1v;
            *(uint4*)&Vs[nb][so] = v0v; *(uint4*)&Vs[nb][so + 32 * 72] = v1v;
        }
        __syncthreads();
    }

    float* cp = ctx_part + ((long)sp * 128 + bh) * 4096;
    #pragma unroll
    for (int mt = 0; mt < 2; mt++) {
        int row = wm + mt * 16 + gid;
        #pragma unroll
        for (int nt = 0; nt < 2; nt++) {
            int col = wn + nt * 8 + 2 * tid4;
            *(float2*)&cp[row * 64 + col] = make_float2(acc[mt][nt][0], acc[mt][nt][1]);
            *(float2*)&cp[(row + 8) * 64 + col] = make_float2(acc[mt][nt][2], acc[mt][nt][3]);
        }
    }
}

// ------------- T[b][d][(h,dd)] = sum_e w_out[d,(h,e)] * ctx[b,h,dd,e] ----
__global__ __launch_bounds__(256) void build_T_kernel(const float* __restrict__ ctx_part,
                                                      const float* __restrict__ rowsum,
                                                      const float* __restrict__ wout,
                                                      __nv_bfloat16* __restrict__ T) {
    int bh = blockIdx.x;
    int b = bh >> 3, h = bh & 7;
    __shared__ float ctxS[64][65];
    __shared__ float wS[64][65];
    int tid = threadIdx.x;

    #pragma unroll
    for (int i = 0; i < 16; i++) {
        int idx = tid + i * 256;
        int d = idx >> 6;
        float s = 0.f;
        #pragma unroll
        for (int sp = 0; sp < NSPLIT; sp++)
            s += ctx_part[((long)sp * 128 + bh) * 4096 + idx];
        ctxS[d][idx & 63] = s / rowsum[b * 512 + h * 64 + d];
    }
    __syncthreads();

    __nv_bfloat16* Tb = T + (long)b * 384 * 512;
    for (int c = 0; c < 6; c++) {
        #pragma unroll
        for (int i = 0; i < 16; i++) {
            int idx = tid + i * 256;
            int dr = idx >> 6, e = idx & 63;
            wS[dr][e] = wout[(long)(c * 64 + dr) * Hh + h * 64 + e];
        }
        __syncthreads();
        #pragma unroll
        for (int i = 0; i < 16; i++) {
            int idx = tid + i * 256;
            int dl = idx >> 6, dd = idx & 63;
            float s = 0.f;
            #pragma unroll
            for (int e = 0; e < 64; e++)
                s += wS[dl][e] * ctxS[dd][e];
            Tb[(long)(c * 64 + dl) * 512 + h * 64 + dd] = __float2bfloat16(s);
        }
        __syncthreads();
    }
}

// -------------------------------------------------------------------------
extern "C" void kernel_launch(void* const* d_in, const int* in_sizes, int n_in,
                              void* d_out, int out_size) {
    (void)in_sizes; (void)n_in; (void)out_size;
    const float* x     = (const float*)d_in[0];
    const float* gam   = (const float*)d_in[1];
    const float* bet   = (const float*)d_in[2];
    const float* w_qkv = (const float*)d_in[3];
    const float* w_out = (const float*)d_in[4];
    const float* b_out = (const float*)d_in[5];
    float* out = (float*)d_out;

    __nv_bfloat16 *p_xn, *p_kv, *p_T, *p_wf, *p_wq;
    float *p_ctxp, *p_rowsum;
    cudaGetSymbolAddress((void**)&p_xn,     g_xn);
    cudaGetSymbolAddress((void**)&p_kv,     g_kv);
    cudaGetSymbolAddress((void**)&p_ctxp,   g_ctxpart);
    cudaGetSymbolAddress((void**)&p_rowsum, g_rowsum);
    cudaGetSymbolAddress((void**)&p_T,      g_T);
    cudaGetSymbolAddress((void**)&p_wf,     g_wf);
    cudaGetSymbolAddress((void**)&p_wq,     g_wqkv_bf);

    // 0. convert w_qkv to bf16
    cvt_kernel<<<(1536 * 384 + 255) / 256, 256>>>(w_qkv, p_wq, 1536 * 384);

    // 1. LN -> bf16 x_norm
    ln_norm_kernel<<<dim3(Nn_ / 32, Bb), 256>>>(x, gam, bet, p_xn);

    // 2. k,v = W_kv @ x_norm  (M=1024, K=384, N=8192), bf16 out
    gemm_bf16_k<0><<<dim3(8, 64, Bb), 256>>>(
        p_wq + (long)512 * Dd, p_xn, p_kv,
        1024, Dd, Nn_,
        0L, (long)Dd * Nn_, (long)1024 * Nn_,
        nullptr, nullptr, 0L, 1.0f);

    // 3. row sums of exp(k)
    rowsum_kernel<<<Bb * 512, 256>>>(p_kv, p_rowsum);

    // 4. partial contexts (tensor cores)
    context_mma_kernel<<<dim3(NSPLIT, 128), 256>>>(p_kv, p_ctxp);

    // 5. T = w_out(head) contracted with normalized ctx
    build_T_kernel<<<128, 256>>>(p_ctxp, p_rowsum, w_out, p_T);

    // 6. W_final[b] = SCALE * T[b] @ W_q  (M=384, K=512, N=384), bf16 out
    gemm_bf16_k<1><<<dim3(3, 3, Bb), 256>>>(
        p_T, p_wq, p_wf,
        384, 512, 384,
        (long)384 * 512, 0L, (long)384 * 384,
        nullptr, nullptr, 0L, SCALE);

    // 7. out = W_final[b] @ x_norm + b_out + x  (M=384, K=384, N=8192)
    gemm_bf16_k<2><<<dim3(3, 64, Bb), 256>>>(
        p_wf, p_xn, out,
        384, Dd, Nn_,
        (long)384 * 384, (long)Dd * Nn_, (long)Dd * Nn_,
        b_out, x, (long)Dd * Nn_, 1.0f);
}

// round 4
// speedup vs baseline: 6.2857x; 1.0579x over previous
#include <cuda_runtime.h>
#include <cuda_bf16.h>
#include <math.h>
#include <stdint.h>

#define Bb 16
#define Dd 384
#define Nn_ 8192
#define Hh 512
#define SCALE 0.125f
#define EPSLN 1e-5f
#define NSPLIT 16

// ---------------- static scratch ----------------
__device__ __nv_bfloat16 g_xn[(long)Bb * Dd * Nn_];        // LN(x), bf16, [b][d][n]
__device__ __nv_bfloat16 g_kv[(long)Bb * 1024 * Nn_];      // rows 0..511 = exp(k), 512..1023 = v
__device__ float         g_ctxpart[(long)NSPLIT * 128 * 4096];
__device__ float         g_rowsum[Bb * 512];
__device__ __nv_bfloat16 g_T[(long)Bb * 384 * 512];
__device__ __nv_bfloat16 g_wf[(long)Bb * 384 * 384];
__device__ __nv_bfloat16 g_wqkv_bf[1536 * 384];

// ---------------- mma.sync helpers ----------------
__device__ __forceinline__ void ldsm_x4(unsigned addr, unsigned &r0, unsigned &r1,
                                        unsigned &r2, unsigned &r3) {
    asm volatile("ldmatrix.sync.aligned.m8n8.x4.shared.b16 {%0,%1,%2,%3}, [%4];\n"
                 : "=r"(r0), "=r"(r1), "=r"(r2), "=r"(r3) : "r"(addr));
}
__device__ __forceinline__ void ldsm_x4_t(unsigned addr, unsigned &r0, unsigned &r1,
                                          unsigned &r2, unsigned &r3) {
    asm volatile("ldmatrix.sync.aligned.m8n8.x4.trans.shared.b16 {%0,%1,%2,%3}, [%4];\n"
                 : "=r"(r0), "=r"(r1), "=r"(r2), "=r"(r3) : "r"(addr));
}
__device__ __forceinline__ void mma16816(float *c, const unsigned *a, unsigned b0, unsigned b1) {
    asm volatile("mma.sync.aligned.m16n8k16.row.col.f32.bf16.bf16.f32 "
                 "{%0,%1,%2,%3}, {%4,%5,%6,%7}, {%8,%9}, {%0,%1,%2,%3};\n"
                 : "+f"(c[0]), "+f"(c[1]), "+f"(c[2]), "+f"(c[3])
                 : "r"(a[0]), "r"(a[1]), "r"(a[2]), "r"(a[3]), "r"(b0), "r"(b1));
}
__device__ __forceinline__ void cpa16(uint32_t s, const void* g) {
    asm volatile("cp.async.cg.shared.global [%0], [%1], 16;" :: "r"(s), "l"(g));
}
__device__ __forceinline__ void cpa_commit() { asm volatile("cp.async.commit_group;" ::: "memory"); }
template<int NN>
__device__ __forceinline__ void cpa_wait() { asm volatile("cp.async.wait_group %0;" :: "n"(NN) : "memory"); }

// ================= 4-stage cp.async bf16 GEMM =================
// C = A(bz)[Mx K row-major] @ B(bz)[K x N row-major]
// EPI 0: bf16 out; if blockIdx.x<4: exp() + rowsum atomics  (GEMM1 kv)
// EPI 1: fp32 out + bias[row] + resid                        (GEMM7 final)
// EPI 2: bf16 out * scale                                    (GEMM6)
#define ASTRIDE 40
#define BSTRIDE 136
#define A_ST_SZ (128 * ASTRIDE)          // halves per stage
#define B_ST_SZ (32 * BSTRIDE)
#define GSMEM_BYTES ((4 * A_ST_SZ + 4 * B_ST_SZ) * 2)

template<int EPI>
__global__ __launch_bounds__(256)
void gemm_cp(const __nv_bfloat16* __restrict__ A, const __nv_bfloat16* __restrict__ B,
             void* __restrict__ Cv, int K, int N,
             long sA, long sB, long sC,
             const float* __restrict__ bias, const float* __restrict__ resid, long sRes,
             float* __restrict__ rowsum, float scale) {
    extern __shared__ __nv_bfloat16 smem[];
    __nv_bfloat16* As = smem;                    // [4][128][ASTRIDE]
    __nv_bfloat16* Bs = smem + 4 * A_ST_SZ;      // [4][32][BSTRIDE]

    int tid = threadIdx.x, lane = tid & 31, wid = tid >> 5;
    int bz = blockIdx.z;
    const __nv_bfloat16* Ab = A + (long)bz * sA;
    const __nv_bfloat16* Bp = B + (long)bz * sB;
    int bm0 = blockIdx.x * 128, bn0 = blockIdx.y * 128;

    // loader indices
    int am = tid >> 2, akq = tid & 3;            // A: 2 chunks (m, m+64)
    int bk = tid >> 4, bnq = tid & 15;           // B: 2 chunks (k, k+16)
    const __nv_bfloat16* Ag0 = Ab + (long)(bm0 + am) * K + akq * 8;
    const __nv_bfloat16* Ag1 = Ag0 + (long)64 * K;
    const __nv_bfloat16* Bg0 = Bp + (long)bk * N + bn0 + bnq * 8;
    const __nv_bfloat16* Bg1 = Bg0 + (long)16 * N;
    uint32_t a_s0 = (uint32_t)__cvta_generic_to_shared(&As[am * ASTRIDE + akq * 8]);
    uint32_t a_s1 = (uint32_t)__cvta_generic_to_shared(&As[(am + 64) * ASTRIDE + akq * 8]);
    uint32_t b_s0 = (uint32_t)__cvta_generic_to_shared(&Bs[bk * BSTRIDE + bnq * 8]);
    uint32_t b_s1 = (uint32_t)__cvta_generic_to_shared(&Bs[(bk + 16) * BSTRIDE + bnq * 8]);

    int nch = K / 32;
    auto load_stage = [&](int c, int buf) {
        int k0 = c * 32;
        cpa16(a_s0 + buf * A_ST_SZ * 2, Ag0 + k0);
        cpa16(a_s1 + buf * A_ST_SZ * 2, Ag1 + k0);
        cpa16(b_s0 + buf * B_ST_SZ * 2, Bg0 + (long)k0 * N);
        cpa16(b_s1 + buf * B_ST_SZ * 2, Bg1 + (long)k0 * N);
        cpa_commit();
    };

    // fragment indices
    int gid = lane >> 2, tid4 = lane & 3;
    int rsel = lane & 15, csel = (lane >> 4) * 8;
    int wm = (wid & 1) * 64, wn = (wid >> 1) * 32;
    uint32_t as_base = (uint32_t)__cvta_generic_to_shared(As);
    uint32_t bs_base = (uint32_t)__cvta_generic_to_shared(Bs);

    float acc[4][4][4];
    #pragma unroll
    for (int i = 0; i < 4; i++)
        #pragma unroll
        for (int j = 0; j < 4; j++)
            #pragma unroll
            for (int k = 0; k < 4; k++) acc[i][j][k] = 0.f;

    load_stage(0, 0);
    load_stage(1, 1);
    load_stage(2, 2);

    #pragma unroll 1
    for (int c = 0; c < nch; c++) {
        int buf = c & 3;
        cpa_wait<2>();
        __syncthreads();
        if (c + 3 < nch) load_stage(c + 3, (c + 3) & 3);
        #pragma unroll
        for (int ks = 0; ks < 32; ks += 16) {
            unsigned a[4][4], bf[2][4];
            #pragma unroll
            for (int mt = 0; mt < 4; mt++) {
                unsigned addr = as_base +
                    (buf * A_ST_SZ + (wm + mt * 16 + rsel) * ASTRIDE + ks + csel) * 2;
                ldsm_x4(addr, a[mt][0], a[mt][1], a[mt][2], a[mt][3]);
            }
            #pragma unroll
            for (int nt2 = 0; nt2 < 2; nt2++) {
                unsigned addr = bs_base +
                    (buf * B_ST_SZ + (ks + rsel) * BSTRIDE + wn + nt2 * 16 + csel) * 2;
                ldsm_x4_t(addr, bf[nt2][0], bf[nt2][1], bf[nt2][2], bf[nt2][3]);
            }
            #pragma unroll
            for (int mt = 0; mt < 4; mt++)
                #pragma unroll
                for (int nt = 0; nt < 4; nt++)
                    mma16816(acc[mt][nt], a[mt], bf[nt >> 1][(nt & 1) * 2],
                             bf[nt >> 1][(nt & 1) * 2 + 1]);
        }
        __syncthreads();
    }

    // ---------------- epilogues ----------------
    if (EPI == 0) {
        __nv_bfloat16* Cb = (__nv_bfloat16*)Cv + (long)bz * sC;
        bool isk = (blockIdx.x < 4);
        float rs[8];
        #pragma unroll
        for (int i = 0; i < 8; i++) rs[i] = 0.f;
        #pragma unroll
        for (int mt = 0; mt < 4; mt++) {
            int row = bm0 + wm + mt * 16 + gid;
            #pragma unroll
            for (int nt = 0; nt < 4; nt++) {
                int col = bn0 + wn + nt * 8 + 2 * tid4;
                float c0 = acc[mt][nt][0], c1 = acc[mt][nt][1];
                float c2 = acc[mt][nt][2], c3 = acc[mt][nt][3];
                if (isk) {
                    c0 = __expf(c0); c1 = __expf(c1);
                    c2 = __expf(c2); c3 = __expf(c3);
                    rs[mt * 2] += c0 + c1;
                    rs[mt * 2 + 1] += c2 + c3;
                }
                *(__nv_bfloat162*)&Cb[(long)row * N + col] = __floats2bfloat162_rn(c0, c1);
                *(__nv_bfloat162*)&Cb[(long)(row + 8) * N + col] = __floats2bfloat162_rn(c2, c3);
            }
        }
        if (isk) {
            #pragma unroll
            for (int i = 0; i < 8; i++) {
                rs[i] += __shfl_xor_sync(0xffffffffu, rs[i], 1);
                rs[i] += __shfl_xor_sync(0xffffffffu, rs[i], 2);
            }
            if (tid4 == 0) {
                #pragma unroll
                for (int mt = 0; mt < 4; mt++) {
                    int row = bm0 + wm + mt * 16 + gid;
                    atomicAdd(&rowsum[bz * 512 + row], rs[mt * 2]);
                    atomicAdd(&rowsum[bz * 512 + row + 8], rs[mt * 2 + 1]);
                }
            }
        }
    } else if (EPI == 1) {
        float* Cf = (float*)Cv + (long)bz * sC;
        const float* rp = resid + (long)bz * sRes;
        #pragma unroll
        for (int mt = 0; mt < 4; mt++) {
            int row = bm0 + wm + mt * 16 + gid;
            float b1 = bias[row], b2 = bias[row + 8];
            #pragma unroll
            for (int nt = 0; nt < 4; nt++) {
                int col = bn0 + wn + nt * 8 + 2 * tid4;
                float2 r1 = *(const float2*)&rp[(long)row * N + col];
                float2 r2 = *(const float2*)&rp[(long)(row + 8) * N + col];
                float2 o1 = make_float2(acc[mt][nt][0] + b1 + r1.x, acc[mt][nt][1] + b1 + r1.y);
                float2 o2 = make_float2(acc[mt][nt][2] + b2 + r2.x, acc[mt][nt][3] + b2 + r2.y);
                *(float2*)&Cf[(long)row * N + col] = o1;
                *(float2*)&Cf[(long)(row + 8) * N + col] = o2;
            }
        }
    } else {
        __nv_bfloat16* Cb = (__nv_bfloat16*)Cv + (long)bz * sC;
        #pragma unroll
        for (int mt = 0; mt < 4; mt++) {
            int row = bm0 + wm + mt * 16 + gid;
            #pragma unroll
            for (int nt = 0; nt < 4; nt++) {
                int col = bn0 + wn + nt * 8 + 2 * tid4;
                *(__nv_bfloat162*)&Cb[(long)row * N + col] =
                    __floats2bfloat162_rn(acc[mt][nt][0] * scale, acc[mt][nt][1] * scale);
                *(__nv_bfloat162*)&Cb[(long)(row + 8) * N + col] =
                    __floats2bfloat162_rn(acc[mt][nt][2] * scale, acc[mt][nt][3] * scale);
            }
        }
    }
}

// ================= small kernels =================
__global__ void cvt_kernel(const float* __restrict__ src, __nv_bfloat16* __restrict__ dst, int n) {
    int i = blockIdx.x * blockDim.x + threadIdx.x;
    if (i < n) dst[i] = __float2bfloat16(src[i]);
}
__global__ void zero_kernel(float* p, int n) {
    int i = blockIdx.x * blockDim.x + threadIdx.x;
    if (i < n) p[i] = 0.f;
}

__global__ __launch_bounds__(256) void ln_norm_kernel(const float* __restrict__ x,
                                                      const float* __restrict__ gamma,
                                                      const float* __restrict__ beta,
                                                      __nv_bfloat16* __restrict__ xn) {
    __shared__ float gS[384], bS[384];
    __shared__ float red_s[8][33], red_q[8][33];
    __shared__ float mS[32], rS[32];
    int tid = threadIdx.x;
    int dg = tid >> 5, tn = tid & 31;
    int b = blockIdx.y;
    int n = blockIdx.x * 32 + tn;
    for (int i = tid; i < 384; i += 256) { gS[i] = gamma[i]; bS[i] = beta[i]; }
    const float* xp = x + (long)b * Dd * Nn_ + n;
    float v[48];
    float s = 0.f, q = 0.f;
    #pragma unroll
    for (int i = 0; i < 48; i++) {
        int d = dg + i * 8;
        v[i] = xp[(long)d * Nn_];
        s += v[i]; q += v[i] * v[i];
    }
    red_s[dg][tn] = s; red_q[dg][tn] = q;
    __syncthreads();
    if (dg == 0) {
        float ts = 0.f, tq = 0.f;
        #pragma unroll
        for (int j = 0; j < 8; j++) { ts += red_s[j][tn]; tq += red_q[j][tn]; }
        float mean = ts * (1.0f / Dd);
        float var = tq * (1.0f / Dd) - mean * mean;
        mS[tn] = mean; rS[tn] = rsqrtf(var + EPSLN);
    }
    __syncthreads();
    float mean = mS[tn], rstd = rS[tn];
    __nv_bfloat16* xo = xn + (long)b * Dd * Nn_ + n;
    #pragma unroll
    for (int i = 0; i < 48; i++) {
        int d = dg + i * 8;
        xo[(long)d * Nn_] = __float2bfloat16((v[i] - mean) * rstd * gS[d] + bS[d]);
    }
}

// ---------------- context via mma.sync (k already exp'd) ----------------
__global__ __launch_bounds__(256) void context_mma_kernel(const __nv_bfloat16* __restrict__ kv,
                                                          float* __restrict__ ctx_part) {
    __shared__ __align__(16) __nv_bfloat16 Ks[2][64 * 72];
    __shared__ __align__(16) __nv_bfloat16 Vs[2][64 * 72];
    const int LEN = Nn_ / NSPLIT;
    int sp = blockIdx.x, bh = blockIdx.y;
    int b = bh >> 3, h = bh & 7;
    const __nv_bfloat16* kb = kv + ((long)b * 1024 + h * 64) * Nn_;
    const __nv_bfloat16* vb = kv + ((long)b * 1024 + 512 + h * 64) * Nn_;
    int tid = threadIdx.x, lane = tid & 31, wid = tid >> 5;
    int lr = tid >> 3, lc = (tid & 7) * 8;
    int n0 = sp * LEN;
    int gid = lane >> 2, tid4 = lane & 3;
    int rsel = lane & 15, csel = (lane >> 4) * 8;
    int wm = (wid & 1) * 32, wn = (wid >> 1) * 16;
    float acc[2][2][4];
    #pragma unroll
    for (int i = 0; i < 2; i++)
        #pragma unroll
        for (int j = 0; j < 2; j++)
            #pragma unroll
            for (int k = 0; k < 4; k++) acc[i][j][k] = 0.f;
    uint4 k0v, k1v, v0v, v1v;
    const int NCH = LEN / 64;
    int so = lr * 72 + lc;
    k0v = *(const uint4*)(kb + (long)lr * Nn_ + n0 + lc);
    k1v = *(const uint4*)(kb + (long)(lr + 32) * Nn_ + n0 + lc);
    v0v = *(const uint4*)(vb + (long)lr * Nn_ + n0 + lc);
    v1v = *(const uint4*)(vb + (long)(lr + 32) * Nn_ + n0 + lc);
    *(uint4*)&Ks[0][so] = k0v; *(uint4*)&Ks[0][so + 32 * 72] = k1v;
    *(uint4*)&Vs[0][so] = v0v; *(uint4*)&Vs[0][so + 32 * 72] = v1v;
    __syncthreads();
    for (int c = 0; c < NCH; c++) {
        int buf = c & 1;
        if (c + 1 < NCH) {
            int off = n0 + (c + 1) * 64 + lc;
            k0v = *(const uint4*)(kb + (long)lr * Nn_ + off);
            k1v = *(const uint4*)(kb + (long)(lr + 32) * Nn_ + off);
            v0v = *(const uint4*)(vb + (long)lr * Nn_ + off);
            v1v = *(const uint4*)(vb + (long)(lr + 32) * Nn_ + off);
        }
        #pragma unroll
        for (int ks = 0; ks < 64; ks += 16) {
            unsigned a[2][4], bf[4];
            #pragma unroll
            for (int mt = 0; mt < 2; mt++) {
                unsigned addr = (unsigned)__cvta_generic_to_shared(
                    &Ks[buf][(wm + mt * 16 + rsel) * 72 + ks + csel]);
                ldsm_x4(addr, a[mt][0], a[mt][1], a[mt][2], a[mt][3]);
            }
            {
                unsigned addr = (unsigned)__cvta_generic_to_shared(
                    &Vs[buf][(wn + rsel) * 72 + ks + csel]);
                ldsm_x4(addr, bf[0], bf[1], bf[2], bf[3]);
            }
            #pragma unroll
            for (int mt = 0; mt < 2; mt++)
                #pragma unroll
                for (int nt = 0; nt < 2; nt++)
                    mma16816(acc[mt][nt], a[mt], bf[nt], bf[nt + 2]);
        }
        if (c + 1 < NCH) {
            int nb = (c + 1) & 1;
            *(uint4*)&Ks[nb][so] = k0v; *(uint4*)&Ks[nb][so + 32 * 72] = k1v;
            *(uint4*)&Vs[nb][so] = v0v; *(uint4*)&Vs[nb][so + 32 * 72] = v1v;
        }
        __syncthreads();
    }
    float* cp = ctx_part + ((long)sp * 128 + bh) * 4096;
    #pragma unroll
    for (int mt = 0; mt < 2; mt++) {
        int row = wm + mt * 16 + gid;
        #pragma unroll
        for (int nt = 0; nt < 2; nt++) {
            int col = wn + nt * 8 + 2 * tid4;
            *(float2*)&cp[row * 64 + col] = make_float2(acc[mt][nt][0], acc[mt][nt][1]);
            *(float2*)&cp[(row + 8) * 64 + col] = make_float2(acc[mt][nt][2], acc[mt][nt][3]);
        }
    }
}

// ------------- T build -------------
__global__ __launch_bounds__(256) void build_T_kernel(const float* __restrict__ ctx_part,
                                                      const float* __restrict__ rowsum,
                                                      const float* __restrict__ wout,
                                                      __nv_bfloat16* __restrict__ T) {
    int bh = blockIdx.x;
    int b = bh >> 3, h = bh & 7;
    __shared__ float ctxS[64][65];
    __shared__ float wS[64][65];
    int tid = threadIdx.x;
    #pragma unroll
    for (int i = 0; i < 16; i++) {
        int idx = tid + i * 256;
        int d = idx >> 6;
        float s = 0.f;
        #pragma unroll
        for (int sp = 0; sp < NSPLIT; sp++)
            s += ctx_part[((long)sp * 128 + bh) * 4096 + idx];
        ctxS[d][idx & 63] = s / rowsum[b * 512 + h * 64 + d];
    }
    __syncthreads();
    __nv_bfloat16* Tb = T + (long)b * 384 * 512;
    for (int c = 0; c < 6; c++) {
        #pragma unroll
        for (int i = 0; i < 16; i++) {
            int idx = tid + i * 256;
            int dr = idx >> 6, e = idx & 63;
            wS[dr][e] = wout[(long)(c * 64 + dr) * Hh + h * 64 + e];
        }
        __syncthreads();
        #pragma unroll
        for (int i = 0; i < 16; i++) {
            int idx = tid + i * 256;
            int dl = idx >> 6, dd = idx & 63;
            float s = 0.f;
            #pragma unroll
            for (int e = 0; e < 64; e++)
                s += wS[dl][e] * ctxS[dd][e];
            Tb[(long)(c * 64 + dl) * 512 + h * 64 + dd] = __float2bfloat16(s);
        }
        __syncthreads();
    }
}

// -------------------------------------------------------------------------
extern "C" void kernel_launch(void* const* d_in, const int* in_sizes, int n_in,
                              void* d_out, int out_size) {
    (void)in_sizes; (void)n_in; (void)out_size;
    const float* x     = (const float*)d_in[0];
    const float* gam   = (const float*)d_in[1];
    const float* bet   = (const float*)d_in[2];
    const float* w_qkv = (const float*)d_in[3];
    const float* w_out = (const float*)d_in[4];
    const float* b_out = (const float*)d_in[5];
    float* out = (float*)d_out;

    __nv_bfloat16 *p_xn, *p_kv, *p_T, *p_wf, *p_wq;
    float *p_ctxp, *p_rowsum;
    cudaGetSymbolAddress((void**)&p_xn,     g_xn);
    cudaGetSymbolAddress((void**)&p_kv,     g_kv);
    cudaGetSymbolAddress((void**)&p_ctxp,   g_ctxpart);
    cudaGetSymbolAddress((void**)&p_rowsum, g_rowsum);
    cudaGetSymbolAddress((void**)&p_T,      g_T);
    cudaGetSymbolAddress((void**)&p_wf,     g_wf);
    cudaGetSymbolAddress((void**)&p_wq,     g_wqkv_bf);

    cudaFuncSetAttribute(gemm_cp<0>, cudaFuncAttributeMaxDynamicSharedMemorySize, GSMEM_BYTES);
    cudaFuncSetAttribute(gemm_cp<1>, cudaFuncAttributeMaxDynamicSharedMemorySize, GSMEM_BYTES);
    cudaFuncSetAttribute(gemm_cp<2>, cudaFuncAttributeMaxDynamicSharedMemorySize, GSMEM_BYTES);

    // 0. prep
    cvt_kernel<<<(1536 * 384 + 255) / 256, 256>>>(w_qkv, p_wq, 1536 * 384);
    zero_kernel<<<(Bb * 512 + 255) / 256, 256>>>(p_rowsum, Bb * 512);

    // 1. LN -> bf16 x_norm
    ln_norm_kernel<<<dim3(Nn_ / 32, Bb), 256>>>(x, gam, bet, p_xn);

    // 2. kv = W_kv @ xn; k half exp'd in epilogue + rowsum atomics
    gemm_cp<0><<<dim3(8, 64, Bb), 256, GSMEM_BYTES>>>(
        p_wq + (long)512 * Dd, p_xn, p_kv, Dd, Nn_,
        0L, (long)Dd * Nn_, (long)1024 * Nn_,
        nullptr, nullptr, 0L, p_rowsum, 1.0f);

    // 3. partial contexts
    context_mma_kernel<<<dim3(NSPLIT, 128), 256>>>(p_kv, p_ctxp);

    // 4. T
    build_T_kernel<<<128, 256>>>(p_ctxp, p_rowsum, w_out, p_T);

    // 5. W_final[b] = SCALE * T[b] @ W_q  (M=384, K=512, N=384)
    gemm_cp<2><<<dim3(3, 3, Bb), 256, GSMEM_BYTES>>>(
        p_T, p_wq, p_wf, 512, 384,
        (long)384 * 512, 0L, (long)384 * 384,
        nullptr, nullptr, 0L, nullptr, SCALE);

    // 6. out = W_final[b] @ xn + b_out + x
    gemm_cp<1><<<dim3(3, 64, Bb), 256, GSMEM_BYTES>>>(
        p_wf, p_xn, out, Dd, Nn_,
        (long)384 * 384, (long)Dd * Nn_, (long)Dd * Nn_,
        b_out, x, (long)Dd * Nn_, nullptr, 1.0f);
}